// round 13
// baseline (speedup 1.0000x reference)
#include <cuda_runtime.h>

#define HH 384
#define WW 384
#define BB 8
#define CC 4
#define NPIX (HH*WW)        // 147456
#define NINST (BB*CC)       // 32
#define BIGF 1e8f
#define DINF (1 << 28)

#define NBLK2 2304          // BB*(HH/2)*WW / 256

// Signed row-pass field, AoS per pixel: g_w[((b*HH+h)*WW+x)*4 + c]
//   = (t==c) ? -dne^2 (or -BIG) : +deq^2 (or +BIG)
// Decode: d1_eq = max(w,0), d1_ne = max(-w,0). Exact.
__device__ float g_w[(unsigned)BB * NPIX * CC];   // ~18.9 MB
__device__ float g_part[NBLK2];

// ---------------------------------------------------------------------------
// Rare-path exact full-row scan (12 words), optional complement.
__device__ int full_scan(const unsigned* __restrict__ words, int x, bool inv) {
    int w0 = x >> 5, b0 = x & 31;
    unsigned wv = words[w0]; if (inv) wv = ~wv;

    int dl = DINF;
    unsigned curl = wv & (0xFFFFFFFFu >> (31 - b0));
    int wl = w0;
    while (curl == 0 && wl > 0) {
        --wl; unsigned t = words[wl]; if (inv) t = ~t; curl = t;
    }
    if (curl) dl = x - (wl * 32 + (31 - __clz(curl)));

    int dr = DINF;
    unsigned curr = wv & (0xFFFFFFFFu << b0);
    int wr = w0;
    while (curr == 0 && wr < 11) {
        ++wr; unsigned t = words[wr]; if (inv) t = ~t; curr = t;
    }
    if (curr) dr = (wr * 32 + (__ffs(curr) - 1)) - x;

    return min(dl, dr);
}

// Min |i-16| over set bits of a 32-bit window (bit 16 = self); DINF if 0.
__device__ __forceinline__ int wdist32(unsigned win) {
    unsigned low  = win & 0x1FFFFu;   // bits 0..16
    unsigned high = win >> 16;        // bits 16..31
    int dl = low  ? (__clz(low) - 15) : DINF;
    int dr = high ? (__ffs(high) - 1) : DINF;
    return min(dl, dr);
}

// ---------------------------------------------------------------------------
// Row pass: one block per (b,h) row; 384 threads. 32-bit funnel-shift windows
// [x-16, x+15]; exact full-scan fallback when window empty (P ~ 1e-4/scan).
// One float4 store per pixel (all 4 classes).
__global__ void k_rowpass(const int* __restrict__ targets) {
    __shared__ unsigned Wp[CC][14];   // padded: [0] and [13] zero

    int b = blockIdx.x / HH;
    int h = blockIdx.x % HH;
    int x = threadIdx.x;
    int warp = x >> 5, lane = x & 31;

    int t = targets[(b * HH + h) * WW + x];

#pragma unroll
    for (int c = 0; c < CC; ++c) {
        unsigned m = __ballot_sync(0xFFFFFFFFu, t == c);
        if (lane == 0) Wp[c][warp + 1] = m;
    }
    if (x < CC) { Wp[x][0] = 0; Wp[x][13] = 0; }
    __syncthreads();

    int start = x - 16;
    int j2 = (start >> 5) + 1;        // padded word index (arithmetic shift ok)
    int sh = start & 31;

    // edge-validity mask (needed only for complement window)
    unsigned em = 0xFFFFFFFFu;
    if (x < 16)  em &= (0xFFFFFFFFu << (16 - x));
    if (x > 368) em &= (0xFFFFFFFFu >> (x - 368));

    // own-class complement distance
    unsigned wno = (~__funnelshift_r(Wp[t][j2], Wp[t][j2 + 1], sh)) & em;
    int dn = wno ? wdist32(wno) : full_scan(&Wp[t][1], x, true);
    float w_own = (dn >= DINF) ? -BIGF : -((float)dn * (float)dn);

    float wout[CC];
#pragma unroll
    for (int c = 0; c < CC; ++c) {
        unsigned we = __funnelshift_r(Wp[c][j2], Wp[c][j2 + 1], sh);
        int de = we ? wdist32(we) : full_scan(&Wp[c][1], x, false);
        float w_eq = (de >= DINF) ? BIGF : ((float)de * (float)de);
        wout[c] = (c == t) ? w_own : w_eq;
    }

    float4 o = make_float4(wout[0], wout[1], wout[2], wout[3]);
    *reinterpret_cast<float4*>(g_w + ((unsigned)(b * HH + h) * WW + x) * 4) = o;
}

// ---------------------------------------------------------------------------
// Col pass: thread owns 2 vertically-adjacent pixels (h0, h0+1). 10 float4
// loads (rows h0-4..h0+5) serve all 4 classes x 2 pixels x 2 polarities.
// dh<=4 straight-line unconditional (extra mins are exact no-ops:
// candidate = v+q >= q >= best); rare exact scalar tail from dh=5.
// Out-of-range rows contribute BIG to both polarities.
__global__ void __launch_bounds__(256) k_loss(const float* __restrict__ logits) {
    int tid = blockIdx.x * 256 + threadIdx.x;     // 0 .. BB*(HH/2)*WW-1
    int b  = tid / ((HH / 2) * WW);
    int rm = tid - b * ((HH / 2) * WW);
    int hg = rm / WW;
    int w  = rm - hg * WW;
    int h0 = hg * 2;

    // ---- 10 shared row loads (float4 = all classes) ----
    float4 vv[10];
    bool valid[10];
#pragma unroll
    for (int i = 0; i < 10; ++i) {
        int r = h0 - 4 + i;
        valid[i] = (r >= 0) && (r < HH);
        int rr = valid[i] ? r : 0;
        vv[i] = __ldg(reinterpret_cast<const float4*>(g_w) +
                      ((unsigned)(b * HH + rr) * WW + w));
    }

    // ---- softmax for both pixels ----
    float pr[2][CC];
#pragma unroll
    for (int j = 0; j < 2; ++j) {
        int rbase = (b * CC) * NPIX + (h0 + j) * WW + w;
        float l0 = logits[rbase];
        float l1 = logits[rbase + NPIX];
        float l2 = logits[rbase + 2 * NPIX];
        float l3 = logits[rbase + 3 * NPIX];
        float mx = fmaxf(fmaxf(l0, l1), fmaxf(l2, l3));
        float e0 = __expf(l0 - mx), e1 = __expf(l1 - mx);
        float e2 = __expf(l2 - mx), e3 = __expf(l3 - mx);
        float inv = 1.0f / (e0 + e1 + e2 + e3);
        pr[j][0] = e0 * inv; pr[j][1] = e1 * inv;
        pr[j][2] = e2 * inv; pr[j][3] = e3 * inv;
    }

    float acc = 0.0f;
#pragma unroll
    for (int c = 0; c < CC; ++c) {
        float bp0 = BIGF, bn0 = BIGF, bp1 = BIGF, bn1 = BIGF;
#pragma unroll
        for (int i = 0; i < 10; ++i) {
            float v = reinterpret_cast<const float*>(&vv[i])[c];
            float vp = valid[i] ? fmaxf(v, 0.0f)  : BIGF;
            float vn = valid[i] ? fmaxf(-v, 0.0f) : BIGF;
            if (i <= 8) {                       // pixel 0: dh = i-4
                float q = (float)((i - 4) * (i - 4));
                bp0 = fminf(bp0, vp + q);
                bn0 = fminf(bn0, vn + q);
            }
            if (i >= 1) {                       // pixel 1: dh = i-5
                float q = (float)((i - 5) * (i - 5));
                bp1 = fminf(bp1, vp + q);
                bn1 = fminf(bn1, vn + q);
            }
        }

        // rare exact tails (per pixel)
#pragma unroll
        for (int j = 0; j < 2; ++j) {
            float bp = j ? bp1 : bp0;
            float bn = j ? bn1 : bn0;
            if (fmaxf(bp, bn) > 25.0f) {
                int h = h0 + j;
                float q = 25.0f, stp = 11.0f;
                int hm = h - 5, hp = h + 5;
#pragma unroll 1
                for (int dh = 5; dh < HH; ++dh) {
                    if (q >= fmaxf(bp, bn)) break;
                    if (hm >= 0) {
                        float v = __ldg(g_w + ((unsigned)(b * HH + hm) * WW + w) * 4 + c);
                        bp = fminf(bp, fmaxf(v, 0.0f) + q);
                        bn = fminf(bn, fmaxf(-v, 0.0f) + q);
                    }
                    if (hp < HH) {
                        float v = __ldg(g_w + ((unsigned)(b * HH + hp) * WW + w) * 4 + c);
                        bp = fminf(bp, fmaxf(v, 0.0f) + q);
                        bn = fminf(bn, fmaxf(-v, 0.0f) + q);
                    }
                    q += stp; stp += 2.0f; --hm; ++hp;
                }
            }
            // Empty/full detection: finite dist^2 <= 2*383^2 ~ 2.9e5 << 1e7;
            // empty-mask surface stays exactly 1e8.
            float phi;
            if (bp >= 1e7f)       phi =  sqrtf(bp);
            else if (bn >= 1e7f)  phi = -sqrtf(bn);
            else                  phi =  sqrtf(bp) - sqrtf(bn) + 1.0f;
            acc += pr[j][c] * phi;
        }
    }

    // block reduction (fixed shape -> deterministic)
    int lane = threadIdx.x & 31, wid = threadIdx.x >> 5;
#pragma unroll
    for (int o = 16; o; o >>= 1) acc += __shfl_down_sync(0xFFFFFFFFu, acc, o);
    __shared__ float sm[8];
    if (lane == 0) sm[wid] = acc;
    __syncthreads();
    if (threadIdx.x < 8) {
        float v = sm[threadIdx.x];
#pragma unroll
        for (int o = 4; o; o >>= 1) v += __shfl_down_sync(0x000000FFu, v, o);
        if (threadIdx.x == 0) g_part[blockIdx.x] = v;
    }
}

// ---------------------------------------------------------------------------
// Final reduce: 9 independent loads per thread (MLP), then add tree.
__global__ void __launch_bounds__(256) k_final(float* __restrict__ out) {
    int t = threadIdx.x;
    float a[9];
#pragma unroll
    for (int i = 0; i < 9; ++i) a[i] = g_part[t + i * 256];
    float s = 0.0f;
#pragma unroll
    for (int i = 0; i < 9; ++i) s += a[i];

    int lane = t & 31, wid = t >> 5;
#pragma unroll
    for (int o = 16; o; o >>= 1) s += __shfl_down_sync(0xFFFFFFFFu, s, o);
    __shared__ float sm[8];
    if (lane == 0) sm[wid] = s;
    __syncthreads();
    if (t < 8) {
        float v = sm[t];
#pragma unroll
        for (int o = 4; o; o >>= 1) v += __shfl_down_sync(0x000000FFu, v, o);
        if (t == 0)
            out[0] = v * (1.0f / ((float)BB * CC * NPIX));
    }
}

// ---------------------------------------------------------------------------
extern "C" void kernel_launch(void* const* d_in, const int* in_sizes, int n_in,
                              void* d_out, int out_size) {
    const float* logits  = (const float*)d_in[0];
    const int*   targets = (const int*)d_in[1];
    float* out = (float*)d_out;

    k_rowpass<<<BB * HH, 384>>>(targets);
    k_loss<<<NBLK2, 256>>>(logits);
    k_final<<<1, 256>>>(out);
}

// round 15
// speedup vs baseline: 1.1294x; 1.1294x over previous
#include <cuda_runtime.h>

#define HH 384
#define WW 384
#define BB 8
#define CC 4
#define NPIX (HH*WW)        // 147456
#define BIGF 1e8f
#define DINF (1 << 28)
#define NBLK3 4608          // BB*NPIX/256

// Signed row-pass field, AoS per pixel: g_w[((b*HH+h)*WW+x)*4 + c]
//   = (t==c) ? -dne^2 (or -BIG) : +deq^2 (or +BIG)
__device__ float g_w[(unsigned)BB * NPIX * CC];   // ~18.9 MB
__device__ float g_part[NBLK3];

// ---------------------------------------------------------------------------
// Rare-path exact full-row scan (12 words), optional complement.
__device__ int full_scan(const unsigned* __restrict__ words, int x, bool inv) {
    int w0 = x >> 5, b0 = x & 31;
    unsigned wv = words[w0]; if (inv) wv = ~wv;

    int dl = DINF;
    unsigned curl = wv & (0xFFFFFFFFu >> (31 - b0));
    int wl = w0;
    while (curl == 0 && wl > 0) {
        --wl; unsigned t = words[wl]; if (inv) t = ~t; curl = t;
    }
    if (curl) dl = x - (wl * 32 + (31 - __clz(curl)));

    int dr = DINF;
    unsigned curr = wv & (0xFFFFFFFFu << b0);
    int wr = w0;
    while (curr == 0 && wr < 11) {
        ++wr; unsigned t = words[wr]; if (inv) t = ~t; curr = t;
    }
    if (curr) dr = (wr * 32 + (__ffs(curr) - 1)) - x;

    return min(dl, dr);
}

// Min |i-16| over set bits of a 32-bit window (bit 16 = self); DINF if 0.
__device__ __forceinline__ int wdist32(unsigned win) {
    unsigned low  = win & 0x1FFFFu;   // bits 0..16
    unsigned high = win >> 16;        // bits 16..31
    int dl = low  ? (__clz(low) - 15) : DINF;
    int dr = high ? (__ffs(high) - 1) : DINF;
    return min(dl, dr);
}

// ---------------------------------------------------------------------------
// Row pass: one block per (b,h) row; 384 threads. 32-bit funnel-shift windows
// [x-16, x+15]; exact full-scan fallback when window empty. For the pixel's
// own class the window is the complement (nearest different-class pixel);
// 4 windows total. One float4 store per pixel.
__global__ void k_rowpass(const int* __restrict__ targets) {
    __shared__ unsigned Wp[CC][14];   // padded: [0] and [13] zero

    int b = blockIdx.x / HH;
    int h = blockIdx.x % HH;
    int x = threadIdx.x;
    int warp = x >> 5, lane = x & 31;

    int t = targets[(b * HH + h) * WW + x];

#pragma unroll
    for (int c = 0; c < CC; ++c) {
        unsigned m = __ballot_sync(0xFFFFFFFFu, t == c);
        if (lane == 0) Wp[c][warp + 1] = m;
    }
    if (x < CC) { Wp[x][0] = 0; Wp[x][13] = 0; }
    __syncthreads();

    int start = x - 16;
    int j2 = (start >> 5) + 1;        // padded word index
    int sh = start & 31;

    // edge-validity mask (needed only for the complement window)
    unsigned em = 0xFFFFFFFFu;
    if (x < 16)  em &= (0xFFFFFFFFu << (16 - x));
    if (x > 368) em &= (0xFFFFFFFFu >> (x - 368));

    float wout[CC];
#pragma unroll
    for (int c = 0; c < CC; ++c) {
        bool own = (c == t);
        unsigned fsh = __funnelshift_r(Wp[c][j2], Wp[c][j2 + 1], sh);
        unsigned win = own ? ((~fsh) & em) : fsh;
        int de = win ? wdist32(win) : full_scan(&Wp[c][1], x, own);
        float val = (de >= DINF) ? BIGF : ((float)de * (float)de);
        wout[c] = own ? -val : val;
    }

    float4 o = make_float4(wout[0], wout[1], wout[2], wout[3]);
    *reinterpret_cast<float4*>(g_w + ((unsigned)(b * HH + h) * WW + x) * 4) = o;
}

// ---------------------------------------------------------------------------
// Single-polarity ring core. After the full 2-D EDT exactly one of pos2/neg2
// is zero per (pixel,class); membership = sign of the center value. Only the
// nonzero polarity is searched: candidate = max(sgn*v + q, q) (fused decode).
// Extra dh<=4 iterations past the true radius are exact no-ops.
template <bool EDGE>
__device__ __forceinline__ float pixel_loss(const float4* __restrict__ gw4,
                                            const float* __restrict__ logits,
                                            int b, int h, int w) {
    // 9 row loads (float4 = all classes), rows h-4..h+4
    float4 vv[9];
#pragma unroll
    for (int i = 0; i < 9; ++i) {
        int r = h - 4 + i;
        int rr = EDGE ? ((r < 0) ? 0 : (r >= HH ? HH - 1 : r)) : r;
        vv[i] = __ldg(gw4 + ((unsigned)(b * HH + rr) * WW + w));
    }

    // softmax
    int rbase = (b * CC) * NPIX + h * WW + w;
    float l0 = logits[rbase];
    float l1 = logits[rbase + NPIX];
    float l2 = logits[rbase + 2 * NPIX];
    float l3 = logits[rbase + 3 * NPIX];
    float mx = fmaxf(fmaxf(l0, l1), fmaxf(l2, l3));
    float e0 = __expf(l0 - mx), e1 = __expf(l1 - mx);
    float e2 = __expf(l2 - mx), e3 = __expf(l3 - mx);
    float inv = 1.0f / (e0 + e1 + e2 + e3);
    float pr[4] = { e0 * inv, e1 * inv, e2 * inv, e3 * inv };

    float acc = 0.0f;
#pragma unroll
    for (int c = 0; c < CC; ++c) {
        float v0 = reinterpret_cast<const float*>(&vv[4])[c];
        float sgn = (v0 < 0.0f) ? -1.0f : 1.0f;
        float best = sgn * v0;                 // = |v0|
#pragma unroll
        for (int i = 0; i < 9; ++i) {
            if (i == 4) continue;
            float q = (float)((i - 4) * (i - 4));
            float v = reinterpret_cast<const float*>(&vv[i])[c];
            float cand = fmaxf(fmaf(sgn, v, q), q);
            if (EDGE) {
                int r = h - 4 + i;
                if (r < 0 || r >= HH) cand = BIGF;
            }
            best = fminf(best, cand);
        }

        // rare exact tail from dh=5 (remaining candidates >= 25)
        if (best > 25.0f) {
            const float* pc = reinterpret_cast<const float*>(gw4) +
                              ((unsigned)(b * HH) * WW + w) * 4 + c;
            float q = 25.0f, stp = 11.0f;
            int hm = h - 5, hp = h + 5;
#pragma unroll 1
            for (int dh = 5; dh < HH; ++dh) {
                if (q >= best) break;
                if (hm >= 0) {
                    float v = __ldg(pc + hm * (WW * 4));
                    best = fminf(best, fmaxf(fmaf(sgn, v, q), q));
                }
                if (hp < HH) {
                    float v = __ldg(pc + hp * (WW * 4));
                    best = fminf(best, fmaxf(fmaf(sgn, v, q), q));
                }
                q += stp; stp += 2.0f; --hm; ++hp;
            }
        }

        // phi = sgn*sqrt(best) (+1 unless degenerate mask: best >= 1e7,
        // finite dist^2 <= 2*383^2 ~ 2.9e5 << 1e7)
        float phi = sgn * sqrtf(best);
        if (best < 1e7f) phi += 1.0f;
        acc += pr[c] * phi;
    }
    return acc;
}

__global__ void __launch_bounds__(256) k_loss(const float* __restrict__ logits) {
    int pid = blockIdx.x * 256 + threadIdx.x;     // 0 .. BB*NPIX-1
    int b = pid / NPIX;
    int r = pid - b * NPIX;
    int h = r / WW;
    int w = r - h * WW;

    const float4* gw4 = reinterpret_cast<const float4*>(g_w);
    float acc;
    if (h >= 4 && h < HH - 4) acc = pixel_loss<false>(gw4, logits, b, h, w);
    else                      acc = pixel_loss<true>(gw4, logits, b, h, w);

    // block reduction (fixed shape -> deterministic)
    int lane = threadIdx.x & 31, wid = threadIdx.x >> 5;
#pragma unroll
    for (int o = 16; o; o >>= 1) acc += __shfl_down_sync(0xFFFFFFFFu, acc, o);
    __shared__ float sm[8];
    if (lane == 0) sm[wid] = acc;
    __syncthreads();
    if (threadIdx.x < 8) {
        float v = sm[threadIdx.x];
#pragma unroll
        for (int o = 4; o; o >>= 1) v += __shfl_down_sync(0x000000FFu, v, o);
        if (threadIdx.x == 0) g_part[blockIdx.x] = v;
    }
}

// ---------------------------------------------------------------------------
// Final reduce: 18 independent loads per thread (MLP), then add tree.
__global__ void __launch_bounds__(256) k_final(float* __restrict__ out) {
    int t = threadIdx.x;
    float a[18];
#pragma unroll
    for (int i = 0; i < 18; ++i) a[i] = g_part[t + i * 256];
    float s = 0.0f;
#pragma unroll
    for (int i = 0; i < 18; ++i) s += a[i];

    int lane = t & 31, wid = t >> 5;
#pragma unroll
    for (int o = 16; o; o >>= 1) s += __shfl_down_sync(0xFFFFFFFFu, s, o);
    __shared__ float sm[8];
    if (lane == 0) sm[wid] = s;
    __syncthreads();
    if (t < 8) {
        float v = sm[t];
#pragma unroll
        for (int o = 4; o; o >>= 1) v += __shfl_down_sync(0x000000FFu, v, o);
        if (t == 0)
            out[0] = v * (1.0f / ((float)BB * CC * NPIX));
    }
}

// ---------------------------------------------------------------------------
extern "C" void kernel_launch(void* const* d_in, const int* in_sizes, int n_in,
                              void* d_out, int out_size) {
    const float* logits  = (const float*)d_in[0];
    const int*   targets = (const int*)d_in[1];
    float* out = (float*)d_out;

    k_rowpass<<<BB * HH, 384>>>(targets);
    k_loss<<<NBLK3, 256>>>(logits);
    k_final<<<1, 256>>>(out);
}

// round 16
// speedup vs baseline: 1.5649x; 1.3856x over previous
#include <cuda_runtime.h>

#define HH 384
#define WW 384
#define BB 8
#define CC 4
#define NPIX (HH*WW)        // 147456
#define BIGF 1e8f
#define DINF (1 << 28)

#define TWD 16              // k_loss tile width
#define THT 16              // k_loss tile height
#define NWT (WW / TWD)      // 24
#define NHT (HH / THT)      // 24
#define NBLK3 (BB * NWT * NHT)   // 4608

// Signed row-pass field, AoS per pixel: g_w[((b*HH+h)*WW+x)*4 + c]
//   = (t==c) ? -dne^2 (or -BIG) : +deq^2 (or +BIG)
__device__ float g_w[(unsigned)BB * NPIX * CC];   // ~18.9 MB
__device__ float g_part[NBLK3];

// ---------------------------------------------------------------------------
// Rare-path exact full-row scan (12 words), optional complement.
__device__ int full_scan(const unsigned* __restrict__ words, int x, bool inv) {
    int w0 = x >> 5, b0 = x & 31;
    unsigned wv = words[w0]; if (inv) wv = ~wv;

    int dl = DINF;
    unsigned curl = wv & (0xFFFFFFFFu >> (31 - b0));
    int wl = w0;
    while (curl == 0 && wl > 0) {
        --wl; unsigned t = words[wl]; if (inv) t = ~t; curl = t;
    }
    if (curl) dl = x - (wl * 32 + (31 - __clz(curl)));

    int dr = DINF;
    unsigned curr = wv & (0xFFFFFFFFu << b0);
    int wr = w0;
    while (curr == 0 && wr < 11) {
        ++wr; unsigned t = words[wr]; if (inv) t = ~t; curr = t;
    }
    if (curr) dr = (wr * 32 + (__ffs(curr) - 1)) - x;

    return min(dl, dr);
}

// Min |i-16| over set bits of a 32-bit window (bit 16 = self); DINF if 0.
__device__ __forceinline__ int wdist32(unsigned win) {
    unsigned low  = win & 0x1FFFFu;   // bits 0..16
    unsigned high = win >> 16;        // bits 16..31
    int dl = low  ? (__clz(low) - 15) : DINF;
    int dr = high ? (__ffs(high) - 1) : DINF;
    return min(dl, dr);
}

// ---------------------------------------------------------------------------
// Row pass: one block per (b,h) row; 384 threads. 32-bit funnel-shift windows
// [x-16, x+15]; exact full-scan fallback when window empty. For the pixel's
// own class the window is the complement (nearest different-class pixel).
// One float4 store per pixel.
__global__ void k_rowpass(const int* __restrict__ targets) {
    __shared__ unsigned Wp[CC][14];   // padded: [0] and [13] zero

    int b = blockIdx.x / HH;
    int h = blockIdx.x % HH;
    int x = threadIdx.x;
    int warp = x >> 5, lane = x & 31;

    int t = targets[(b * HH + h) * WW + x];

#pragma unroll
    for (int c = 0; c < CC; ++c) {
        unsigned m = __ballot_sync(0xFFFFFFFFu, t == c);
        if (lane == 0) Wp[c][warp + 1] = m;
    }
    if (x < CC) { Wp[x][0] = 0; Wp[x][13] = 0; }
    __syncthreads();

    int start = x - 16;
    int j2 = (start >> 5) + 1;        // padded word index
    int sh = start & 31;

    // edge-validity mask (needed only for the complement window)
    unsigned em = 0xFFFFFFFFu;
    if (x < 16)  em &= (0xFFFFFFFFu << (16 - x));
    if (x > 368) em &= (0xFFFFFFFFu >> (x - 368));

    float wout[CC];
#pragma unroll
    for (int c = 0; c < CC; ++c) {
        bool own = (c == t);
        unsigned fsh = __funnelshift_r(Wp[c][j2], Wp[c][j2 + 1], sh);
        unsigned win = own ? ((~fsh) & em) : fsh;
        int de = win ? wdist32(win) : full_scan(&Wp[c][1], x, own);
        float val = (de >= DINF) ? BIGF : ((float)de * (float)de);
        wout[c] = own ? -val : val;
    }

    float4 o = make_float4(wout[0], wout[1], wout[2], wout[3]);
    *reinterpret_cast<float4*>(g_w + ((unsigned)(b * HH + h) * WW + x) * 4) = o;
}

// ---------------------------------------------------------------------------
// Single-polarity ring core. After the full 2-D EDT exactly one of pos2/neg2
// is zero per (pixel,class); membership = sign of the center value. Only the
// nonzero polarity is searched: candidate = max(sgn*v + q, q) (fused decode).
// Extra dh<=4 iterations past the true radius are exact no-ops.
template <bool EDGE>
__device__ __forceinline__ float pixel_loss(const float4* __restrict__ gw4,
                                            const float* __restrict__ logits,
                                            int b, int h, int w) {
    // 9 row loads (float4 = all classes), rows h-4..h+4
    float4 vv[9];
#pragma unroll
    for (int i = 0; i < 9; ++i) {
        int r = h - 4 + i;
        int rr = EDGE ? ((r < 0) ? 0 : (r >= HH ? HH - 1 : r)) : r;
        vv[i] = __ldg(gw4 + ((unsigned)(b * HH + rr) * WW + w));
    }

    // softmax
    int rbase = (b * CC) * NPIX + h * WW + w;
    float l0 = logits[rbase];
    float l1 = logits[rbase + NPIX];
    float l2 = logits[rbase + 2 * NPIX];
    float l3 = logits[rbase + 3 * NPIX];
    float mx = fmaxf(fmaxf(l0, l1), fmaxf(l2, l3));
    float e0 = __expf(l0 - mx), e1 = __expf(l1 - mx);
    float e2 = __expf(l2 - mx), e3 = __expf(l3 - mx);
    float inv = 1.0f / (e0 + e1 + e2 + e3);
    float pr[4] = { e0 * inv, e1 * inv, e2 * inv, e3 * inv };

    float acc = 0.0f;
#pragma unroll
    for (int c = 0; c < CC; ++c) {
        float v0 = reinterpret_cast<const float*>(&vv[4])[c];
        float sgn = (v0 < 0.0f) ? -1.0f : 1.0f;
        float best = sgn * v0;                 // = |v0|
#pragma unroll
        for (int i = 0; i < 9; ++i) {
            if (i == 4) continue;
            float q = (float)((i - 4) * (i - 4));
            float v = reinterpret_cast<const float*>(&vv[i])[c];
            float cand = fmaxf(fmaf(sgn, v, q), q);
            if (EDGE) {
                int r = h - 4 + i;
                if (r < 0 || r >= HH) cand = BIGF;
            }
            best = fminf(best, cand);
        }

        // rare exact tail from dh=5 (remaining candidates >= 25)
        if (best > 25.0f) {
            const float* pc = reinterpret_cast<const float*>(gw4) +
                              ((unsigned)(b * HH) * WW + w) * 4 + c;
            float q = 25.0f, stp = 11.0f;
            int hm = h - 5, hp = h + 5;
#pragma unroll 1
            for (int dh = 5; dh < HH; ++dh) {
                if (q >= best) break;
                if (hm >= 0) {
                    float v = __ldg(pc + hm * (WW * 4));
                    best = fminf(best, fmaxf(fmaf(sgn, v, q), q));
                }
                if (hp < HH) {
                    float v = __ldg(pc + hp * (WW * 4));
                    best = fminf(best, fmaxf(fmaf(sgn, v, q), q));
                }
                q += stp; stp += 2.0f; --hm; ++hp;
            }
        }

        // phi = sgn*sqrt(best) (+1 unless degenerate mask: best >= 1e7,
        // finite dist^2 <= 2*383^2 ~ 2.9e5 << 1e7)
        float phi = sgn * sqrtf(best);
        if (best < 1e7f) phi += 1.0f;
        acc += pr[c] * phi;
    }
    return acc;
}

// 2-D tiled mapping: block = 16w x 16h tile of one batch image. The 9-row
// windows of the tile's 16 h-values span only 24 distinct rows -> halo
// amplification 1.5x (was 9x with row-major pid), slab (~6KB) L1-resident.
__global__ void __launch_bounds__(256) k_loss(const float* __restrict__ logits) {
    int bt = blockIdx.x;
    int b  = bt / (NWT * NHT);
    int tr = bt - b * (NWT * NHT);
    int ht = tr / NWT;
    int wt = tr - ht * NWT;

    int wl = threadIdx.x & (TWD - 1);
    int hl = threadIdx.x >> 4;
    int w = wt * TWD + wl;
    int h = ht * THT + hl;

    const float4* gw4 = reinterpret_cast<const float4*>(g_w);
    float acc;
    if (ht >= 1 && ht < NHT - 1) acc = pixel_loss<false>(gw4, logits, b, h, w);
    else                         acc = pixel_loss<true>(gw4, logits, b, h, w);

    // block reduction (fixed shape -> deterministic)
    int lane = threadIdx.x & 31, wid = threadIdx.x >> 5;
#pragma unroll
    for (int o = 16; o; o >>= 1) acc += __shfl_down_sync(0xFFFFFFFFu, acc, o);
    __shared__ float sm[8];
    if (lane == 0) sm[wid] = acc;
    __syncthreads();
    if (threadIdx.x < 8) {
        float v = sm[threadIdx.x];
#pragma unroll
        for (int o = 4; o; o >>= 1) v += __shfl_down_sync(0x000000FFu, v, o);
        if (threadIdx.x == 0) g_part[blockIdx.x] = v;
    }
}

// ---------------------------------------------------------------------------
// Final reduce: 18 independent loads per thread (MLP), then add tree.
__global__ void __launch_bounds__(256) k_final(float* __restrict__ out) {
    int t = threadIdx.x;
    float a[18];
#pragma unroll
    for (int i = 0; i < 18; ++i) a[i] = g_part[t + i * 256];
    float s = 0.0f;
#pragma unroll
    for (int i = 0; i < 18; ++i) s += a[i];

    int lane = t & 31, wid = t >> 5;
#pragma unroll
    for (int o = 16; o; o >>= 1) s += __shfl_down_sync(0xFFFFFFFFu, s, o);
    __shared__ float sm[8];
    if (lane == 0) sm[wid] = s;
    __syncthreads();
    if (t < 8) {
        float v = sm[t];
#pragma unroll
        for (int o = 4; o; o >>= 1) v += __shfl_down_sync(0x000000FFu, v, o);
        if (t == 0)
            out[0] = v * (1.0f / ((float)BB * CC * NPIX));
    }
}

// ---------------------------------------------------------------------------
extern "C" void kernel_launch(void* const* d_in, const int* in_sizes, int n_in,
                              void* d_out, int out_size) {
    const float* logits  = (const float*)d_in[0];
    const int*   targets = (const int*)d_in[1];
    float* out = (float*)d_out;

    k_rowpass<<<BB * HH, 384>>>(targets);
    k_loss<<<NBLK3, 256>>>(logits);
    k_final<<<1, 256>>>(out);
}